// round 7
// baseline (speedup 1.0000x reference)
#include <cuda_runtime.h>
#include <cuda_bf16.h>
#include <cstdint>

// Fixed problem shape: N=50000, IN_CH=256, OUT_CH=128, NNZ=800000 per matrix.
#define NNODES 50000
#define FEAT   128
#define MAXNNZ 800000
#define TOT    (NNODES * FEAT)
#define SLOTS  64                  // per-row bucket capacity (Poisson(16): P(>64) ~ 1e-22)
#define FULLM  0xFFFFFFFFu

// ---------------------------------------------------------------------------
// Static device scratch. m=0 features, m=1 phi_inv, m=2 phi.
// ---------------------------------------------------------------------------
__device__ float g_buf0[TOT];                         // filtered  [N,128]
__device__ float g_buf1[TOT];                         // tmp       [N,128]
__device__ int   g_cursor[3 * NNODES];                // per-row fill cursors == counts
__device__ int2  g_slots[3 * NNODES * SLOTS];         // (col, val-bits) buckets

// ---------------------------------------------------------------------------
// Zero the cursors (600 KB).
// ---------------------------------------------------------------------------
__global__ void zero_cursor_kernel() {
    int i = blockIdx.x * blockDim.x + threadIdx.x;
    if (i < 3 * NNODES) g_cursor[i] = 0;
}

// ---------------------------------------------------------------------------
// Fused bucket-scatter for all three matrices. blockIdx.y selects the matrix.
// 4 nnz per thread for ILP. theta (matrix 2) folds phi @ diag(theta) in.
// ---------------------------------------------------------------------------
__global__ void scatter_kernel(const int*   __restrict__ rows0, const float* __restrict__ vals0, int nnz0,
                               const int*   __restrict__ rows1, const float* __restrict__ vals1, int nnz1,
                               const int*   __restrict__ rows2, const float* __restrict__ vals2, int nnz2,
                               const float* __restrict__ theta) {
    const int m = blockIdx.y;
    const int* rows; const int* cols; const float* vals; int nnz;
    const float* th = nullptr;
    if (m == 0)      { rows = rows0; cols = rows0 + nnz0; vals = vals0; nnz = nnz0; }
    else if (m == 1) { rows = rows1; cols = rows1 + nnz1; vals = vals1; nnz = nnz1; }
    else             { rows = rows2; cols = rows2 + nnz2; vals = vals2; nnz = nnz2; th = theta; }

    int base = (blockIdx.x * blockDim.x + threadIdx.x) * 4;
    if (base >= nnz) return;

    int*  cur   = g_cursor + m * NNODES;
    int2* slots = g_slots + (size_t)m * NNODES * SLOTS;

    if (base + 4 <= nnz) {
        int4   r4 = *reinterpret_cast<const int4*>(rows + base);
        int4   c4 = *reinterpret_cast<const int4*>(cols + base);
        float4 v4 = *reinterpret_cast<const float4*>(vals + base);
        int   r[4] = {r4.x, r4.y, r4.z, r4.w};
        int   c[4] = {c4.x, c4.y, c4.z, c4.w};
        float v[4] = {v4.x, v4.y, v4.z, v4.w};
        #pragma unroll
        for (int k = 0; k < 4; k++) {
            float vv = v[k];
            if (th) vv *= __ldg(th + c[k]);
            int pos = atomicAdd(cur + r[k], 1);
            slots[(size_t)r[k] * SLOTS + pos] = make_int2(c[k], __float_as_int(vv));
        }
    } else {
        for (int i = base; i < nnz && i < base + 4; i++) {
            int r = __ldg(rows + i);
            int c = __ldg(cols + i);
            float vv = __ldg(vals + i);
            if (th) vv *= __ldg(th + c);
            int pos = atomicAdd(cur + r, 1);
            slots[(size_t)r * SLOTS + pos] = make_int2(c, __float_as_int(vv));
        }
    }
}

// ---------------------------------------------------------------------------
// Gather SpMM: out[row,:] = sum_j val_j * dense[col_j, :]   (F = 128)
// One warp per row. Lane i prefetches entry i with a single coalesced 8B
// load; cols/vals broadcast via shfl (register-resident). The main loop
// keeps EIGHT independent float4 loads in flight per batch, so a typical
// 16-nnz row completes in two exposed-latency rounds. ReLU optionally fused.
// ---------------------------------------------------------------------------
template <bool RELU>
__global__ void spmm_gather_kernel(int m,
                                   const float* __restrict__ dense,
                                   float*       __restrict__ out) {
    int row  = (blockIdx.x * blockDim.x + threadIdx.x) >> 5;
    int lane = threadIdx.x & 31;
    if (row >= NNODES) return;

    int cnt = __ldg(g_cursor + m * NNODES + row);
    if (cnt > SLOTS) cnt = SLOTS;
    const int2* e = g_slots + (size_t)m * NNODES * SLOTS + (size_t)row * SLOTS;

    // One coalesced load covers entries 0..31 for the whole warp.
    int2 my_e = make_int2(0, 0);
    if (lane < cnt) my_e = __ldg(e + lane);

    float4 acc0 = make_float4(0.f, 0.f, 0.f, 0.f);
    float4 acc1 = make_float4(0.f, 0.f, 0.f, 0.f);

    const int n32 = (cnt < 32) ? cnt : 32;
    int i = 0;

    // 8-deep MLP batches
    for (; i + 8 <= n32; i += 8) {
        int   c[8];
        float v[8];
        #pragma unroll
        for (int k = 0; k < 8; k++) {
            c[k] = __shfl_sync(FULLM, my_e.x, i + k);
            v[k] = __int_as_float(__shfl_sync(FULLM, my_e.y, i + k));
        }
        float4 x[8];
        #pragma unroll
        for (int k = 0; k < 8; k++)
            x[k] = __ldg(reinterpret_cast<const float4*>(dense + (size_t)c[k] * FEAT) + lane);
        #pragma unroll
        for (int k = 0; k < 8; k += 2) {
            acc0.x += v[k] * x[k].x;     acc0.y += v[k] * x[k].y;
            acc0.z += v[k] * x[k].z;     acc0.w += v[k] * x[k].w;
            acc1.x += v[k+1] * x[k+1].x; acc1.y += v[k+1] * x[k+1].y;
            acc1.z += v[k+1] * x[k+1].z; acc1.w += v[k+1] * x[k+1].w;
        }
    }
    // 4-deep remainder batch
    if (i + 4 <= n32) {
        int   c[4];
        float v[4];
        #pragma unroll
        for (int k = 0; k < 4; k++) {
            c[k] = __shfl_sync(FULLM, my_e.x, i + k);
            v[k] = __int_as_float(__shfl_sync(FULLM, my_e.y, i + k));
        }
        float4 x[4];
        #pragma unroll
        for (int k = 0; k < 4; k++)
            x[k] = __ldg(reinterpret_cast<const float4*>(dense + (size_t)c[k] * FEAT) + lane);
        #pragma unroll
        for (int k = 0; k < 4; k += 2) {
            acc0.x += v[k] * x[k].x;     acc0.y += v[k] * x[k].y;
            acc0.z += v[k] * x[k].z;     acc0.w += v[k] * x[k].w;
            acc1.x += v[k+1] * x[k+1].x; acc1.y += v[k+1] * x[k+1].y;
            acc1.z += v[k+1] * x[k+1].z; acc1.w += v[k+1] * x[k+1].w;
        }
        i += 4;
    }
    // scalar remainder
    for (; i < n32; i++) {
        int   c0 = __shfl_sync(FULLM, my_e.x, i);
        float v0 = __int_as_float(__shfl_sync(FULLM, my_e.y, i));
        float4 x0 = __ldg(reinterpret_cast<const float4*>(dense + (size_t)c0 * FEAT) + lane);
        acc0.x += v0 * x0.x; acc0.y += v0 * x0.y; acc0.z += v0 * x0.z; acc0.w += v0 * x0.w;
    }
    // Rare tail: rows with more than 32 entries (~1e-4 of rows).
    for (; i < cnt; i++) {
        int2 ee = __ldg(e + i);
        float vv = __int_as_float(ee.y);
        float4 x0 = __ldg(reinterpret_cast<const float4*>(dense + (size_t)ee.x * FEAT) + lane);
        acc0.x += vv * x0.x; acc0.y += vv * x0.y; acc0.z += vv * x0.z; acc0.w += vv * x0.w;
    }

    float4 r;
    r.x = acc0.x + acc1.x;
    r.y = acc0.y + acc1.y;
    r.z = acc0.z + acc1.z;
    r.w = acc0.w + acc1.w;
    if (RELU) {
        r.x = fmaxf(r.x, 0.f); r.y = fmaxf(r.y, 0.f);
        r.z = fmaxf(r.z, 0.f); r.w = fmaxf(r.w, 0.f);
    }
    reinterpret_cast<float4*>(out + (size_t)row * FEAT)[lane] = r;
}

// ---------------------------------------------------------------------------
// Launch sequence (graph-capturable).
// Inputs:
//   0 phi_indices int32[2,NNZ]  1 phi_values f32[NNZ]
//   2 phi_inv_indices           3 phi_inv_values
//   4 feature_indices           5 feature_values
//   6 weight_matrix f32[256,128] 7 theta f32[N]  8 dropout (ignored)
// ---------------------------------------------------------------------------
extern "C" void kernel_launch(void* const* d_in, const int* in_sizes, int n_in,
                              void* d_out, int out_size) {
    const int*   phi_idx    = (const int*)  d_in[0];
    const float* phi_vals   = (const float*)d_in[1];
    const int*   phinv_idx  = (const int*)  d_in[2];
    const float* phinv_vals = (const float*)d_in[3];
    const int*   feat_idx   = (const int*)  d_in[4];
    const float* feat_vals  = (const float*)d_in[5];
    const float* W          = (const float*)d_in[6];
    const float* theta      = (const float*)d_in[7];
    float*       out        = (float*)d_out;

    const int nnz_phi   = in_sizes[1];
    const int nnz_phinv = in_sizes[3];
    const int nnz_feat  = in_sizes[5];

    float* buf0 = nullptr; float* buf1 = nullptr;
    cudaGetSymbolAddress((void**)&buf0, g_buf0);
    cudaGetSymbolAddress((void**)&buf1, g_buf1);

    const int B = 256;

    // 1) zero per-row cursors
    zero_cursor_kernel<<<(3 * NNODES + B - 1) / B, B>>>();

    // 2) fused bucket scatter for all three matrices
    int nnz_max = nnz_feat;
    if (nnz_phinv > nnz_max) nnz_max = nnz_phinv;
    if (nnz_phi   > nnz_max) nnz_max = nnz_phi;
    dim3 sgrid((nnz_max + 4 * B - 1) / (4 * B), 3);
    scatter_kernel<<<sgrid, B>>>(feat_idx,  feat_vals,  nnz_feat,
                                 phinv_idx, phinv_vals, nnz_phinv,
                                 phi_idx,   phi_vals,   nnz_phi,
                                 theta);

    // 3) three gather SpMMs; ReLU fused into the last
    const int SG = (NNODES * 32 + B - 1) / B;    // warp per row
    spmm_gather_kernel<false><<<SG, B>>>(0, W,    buf0);
    spmm_gather_kernel<false><<<SG, B>>>(1, buf0, buf1);
    spmm_gather_kernel<true ><<<SG, B>>>(2, buf1, out);
}